// round 11
// baseline (speedup 1.0000x reference)
#include <cuda_runtime.h>
#include <cuda_bf16.h>

// Problem: out[b] = bias + sum_{t in unique(text[:, b])} W[t]
//   text: [L=200, B=4096] int32 row-major (JAX x64-disabled downcasts int64),
//         values in [0, 50000)
//   W:    [1, 50000] float32
//   b:    [1] float32
//   out:  [B, 1] float32
//
// Strategy: 8 docs per block (256 threads). Shared-memory bitset per doc
// (1563 words, padded to 1564 for uint4 zeroing). atomicOr's old value gives
// the first-occurrence predicate; gather W only on first occurrence.
// Thread t handles doc (t & 7), so 8 adjacent lanes read 8 consecutive
// int32 from the same text row -> fully coalesced 32B segments.

#define L_SEQ 200
#define BATCH 4096
#define VOCAB 50000
#define DOCS_PER_BLOCK 8
#define THREADS 256
#define BITMAP_WORDS 1564                      // ceil(50000/32)=1563, pad to %4==0
#define SMEM_WORDS (DOCS_PER_BLOCK * BITMAP_WORDS)
#define SMEM_BYTES (SMEM_WORDS * 4 + DOCS_PER_BLOCK * 4)

__global__ void __launch_bounds__(THREADS, 4)
doc_presence_dot_kernel(const int* __restrict__ text,
                        const float* __restrict__ W,
                        const float* __restrict__ bias,
                        float* __restrict__ out)
{
    extern __shared__ unsigned smem[];
    unsigned* bitmap = smem;                       // [DOCS_PER_BLOCK][BITMAP_WORDS] flat
    float* acc = (float*)(smem + SMEM_WORDS);      // [DOCS_PER_BLOCK]

    const int tid = threadIdx.x;
    const int doc = tid & 7;                       // doc within block
    const int b0  = blockIdx.x * DOCS_PER_BLOCK;   // first global doc of block

    // Zero bitmaps with 128-bit stores: SMEM_WORDS/4 = 3128 uint4
    {
        uint4 z = make_uint4(0u, 0u, 0u, 0u);
        uint4* p = (uint4*)smem;
        #pragma unroll
        for (int i = tid; i < SMEM_WORDS / 4; i += THREADS)
            p[i] = z;
        if (tid < DOCS_PER_BLOCK) acc[tid] = 0.0f;
    }
    __syncthreads();

    // i % 8 == tid % 8 always (stride 256 is a multiple of 8), so all of a
    // thread's tokens belong to the same doc -> local accumulation works.
    float sum = 0.0f;
    unsigned* my_bitmap = bitmap + doc * BITMAP_WORDS;
    #pragma unroll 2
    for (int i = tid; i < L_SEQ * DOCS_PER_BLOCK; i += THREADS) {
        const int l = i >> 3;
        const int t = text[l * BATCH + b0 + doc];
        const unsigned mask = 1u << (t & 31);
        const unsigned old = atomicOr(&my_bitmap[t >> 5], mask);
        if (!(old & mask))
            sum += __ldg(&W[t]);
    }

    // Intra-warp reduce over lanes sharing the same doc (lane, lane^8, lane^16)
    sum += __shfl_xor_sync(0xffffffffu, sum, 8);
    sum += __shfl_xor_sync(0xffffffffu, sum, 16);
    // Lanes 0..7 of each warp hold the warp's per-doc partial
    if ((tid & 31) < DOCS_PER_BLOCK)
        atomicAdd(&acc[doc], sum);
    __syncthreads();

    if (tid < DOCS_PER_BLOCK)
        out[b0 + tid] = acc[tid] + bias[0];
}

extern "C" void kernel_launch(void* const* d_in, const int* in_sizes, int n_in,
                              void* d_out, int out_size)
{
    const int*   text = (const int*)d_in[0];
    const float* W    = (const float*)d_in[1];
    const float* bias = (const float*)d_in[2];
    float*       out  = (float*)d_out;

    (void)in_sizes; (void)n_in; (void)out_size;

    static bool attr_set = false;
    if (!attr_set) {
        cudaFuncSetAttribute(doc_presence_dot_kernel,
                             cudaFuncAttributeMaxDynamicSharedMemorySize, SMEM_BYTES);
        attr_set = true;
    }

    dim3 grid(BATCH / DOCS_PER_BLOCK);  // 512 blocks
    doc_presence_dot_kernel<<<grid, THREADS, SMEM_BYTES>>>(text, W, bias, out);
}

// round 12
// speedup vs baseline: 1.0477x; 1.0477x over previous
#include <cuda_runtime.h>
#include <cuda_bf16.h>

// Problem: out[b] = bias + sum_{t in unique(text[:, b])} W[t]
//   text: [L=200, B=4096] int32 row-major (JAX x64-disabled downcasts int64),
//         values in [0, 50000)
//   W:    [1, 50000] float32
//   b:    [1] float32
//   out:  [B, 1] float32
//
// Strategy: 8 docs per block (256 threads). Shared-memory bitset per doc
// (1563 words, padded to 1564 for uint4 zeroing). atomicOr's old value gives
// the first-occurrence predicate; gather W only on first occurrence.
// Thread t handles doc (t & 7), so 8 adjacent lanes read 8 consecutive
// int32 from the same text row -> fully coalesced 32B segments.

#define L_SEQ 200
#define BATCH 4096
#define VOCAB 50000
#define DOCS_PER_BLOCK 8
#define THREADS 256
#define BITMAP_WORDS 1564                      // ceil(50000/32)=1563, pad to %4==0
#define SMEM_WORDS (DOCS_PER_BLOCK * BITMAP_WORDS)
#define SMEM_BYTES (SMEM_WORDS * 4 + DOCS_PER_BLOCK * 4)

__global__ void __launch_bounds__(THREADS, 4)
doc_presence_dot_kernel(const int* __restrict__ text,
                        const float* __restrict__ W,
                        const float* __restrict__ bias,
                        float* __restrict__ out)
{
    extern __shared__ unsigned smem[];
    unsigned* bitmap = smem;                       // [DOCS_PER_BLOCK][BITMAP_WORDS] flat
    float* acc = (float*)(smem + SMEM_WORDS);      // [DOCS_PER_BLOCK]

    const int tid = threadIdx.x;
    const int doc = tid & 7;                       // doc within block
    const int b0  = blockIdx.x * DOCS_PER_BLOCK;   // first global doc of block

    // Zero bitmaps with 128-bit stores: SMEM_WORDS/4 = 3128 uint4
    {
        uint4 z = make_uint4(0u, 0u, 0u, 0u);
        uint4* p = (uint4*)smem;
        #pragma unroll
        for (int i = tid; i < SMEM_WORDS / 4; i += THREADS)
            p[i] = z;
        if (tid < DOCS_PER_BLOCK) acc[tid] = 0.0f;
    }
    __syncthreads();

    // i % 8 == tid % 8 always (stride 256 is a multiple of 8), so all of a
    // thread's tokens belong to the same doc -> local accumulation works.
    float sum = 0.0f;
    unsigned* my_bitmap = bitmap + doc * BITMAP_WORDS;
    #pragma unroll 2
    for (int i = tid; i < L_SEQ * DOCS_PER_BLOCK; i += THREADS) {
        const int l = i >> 3;
        const int t = text[l * BATCH + b0 + doc];
        const unsigned mask = 1u << (t & 31);
        const unsigned old = atomicOr(&my_bitmap[t >> 5], mask);
        if (!(old & mask))
            sum += __ldg(&W[t]);
    }

    // Intra-warp reduce over lanes sharing the same doc (lane, lane^8, lane^16)
    sum += __shfl_xor_sync(0xffffffffu, sum, 8);
    sum += __shfl_xor_sync(0xffffffffu, sum, 16);
    // Lanes 0..7 of each warp hold the warp's per-doc partial
    if ((tid & 31) < DOCS_PER_BLOCK)
        atomicAdd(&acc[doc], sum);
    __syncthreads();

    if (tid < DOCS_PER_BLOCK)
        out[b0 + tid] = acc[tid] + bias[0];
}

extern "C" void kernel_launch(void* const* d_in, const int* in_sizes, int n_in,
                              void* d_out, int out_size)
{
    const int*   text = (const int*)d_in[0];
    const float* W    = (const float*)d_in[1];
    const float* bias = (const float*)d_in[2];
    float*       out  = (float*)d_out;

    (void)in_sizes; (void)n_in; (void)out_size;

    static bool attr_set = false;
    if (!attr_set) {
        cudaFuncSetAttribute(doc_presence_dot_kernel,
                             cudaFuncAttributeMaxDynamicSharedMemorySize, SMEM_BYTES);
        attr_set = true;
    }

    dim3 grid(BATCH / DOCS_PER_BLOCK);  // 512 blocks
    doc_presence_dot_kernel<<<grid, THREADS, SMEM_BYTES>>>(text, W, bias, out);
}